// round 1
// baseline (speedup 1.0000x reference)
#include <cuda_runtime.h>
#include <cuda_bf16.h>

// SKA: spatially-varying 3x3 grouped conv.
// x: (B=8, C=64, H=128, W=128) f32
// w: (B=8, C_w=8, 9, H, W) f32
// out[b, g*8+cw, h, x] = sum_{i,j} x_pad[b, g*8+cw, h+i, x+j] * w[b, cw, i*3+j, h, x]
//
// Thread = (b, cw, h, wq) where wq indexes a 4-wide float4 chunk of the row.
// 9 weights (float4 each) loaded once into registers, reused across all 8 groups.

#define B_   8
#define C_   64
#define H_   128
#define W_   128
#define CW_  8
#define G_   8
#define HW_  (H_ * W_)

__global__ void __launch_bounds__(256) ska_kernel(
    const float* __restrict__ x,
    const float* __restrict__ w,
    float* __restrict__ out)
{
    int gid = blockIdx.x * blockDim.x + threadIdx.x;
    // total threads = B * CW * H * (W/4) = 8*8*128*32 = 262144
    int wq = gid & 31;          // 0..31  (float4 chunk within row)
    int h  = (gid >> 5) & 127;  // 0..127
    int cw = (gid >> 12) & 7;   // 0..7
    int b  = gid >> 15;         // 0..7
    int col0 = wq << 2;

    // ---- load the 9 per-pixel weights (float4 across 4 output columns) ----
    const float* wbase = w + ((size_t)(b * CW_ + cw) * 9) * HW_ + h * W_ + col0;
    float4 wv[9];
#pragma unroll
    for (int k = 0; k < 9; k++) {
        wv[k] = *reinterpret_cast<const float4*>(wbase + (size_t)k * HW_);
    }

    const bool hasL = (wq != 0);
    const bool hasR = (wq != 31);

    const float* xb = x + (size_t)b * C_ * HW_;
    float* ob = out + (size_t)b * C_ * HW_;

#pragma unroll 2
    for (int g = 0; g < G_; g++) {
        int c = g * CW_ + cw;
        const float* xc = xb + (size_t)c * HW_;

        // r[di][0..5] = x[h+di-1][col0-1 .. col0+4], zero-padded at borders
        float r[3][6];
#pragma unroll
        for (int di = 0; di < 3; di++) {
            int hh = h + di - 1;
            if (hh >= 0 && hh < H_) {
                const float* xr = xc + hh * W_ + col0;
                float4 v = *reinterpret_cast<const float4*>(xr);
                r[di][1] = v.x; r[di][2] = v.y; r[di][3] = v.z; r[di][4] = v.w;
                r[di][0] = hasL ? xr[-1] : 0.0f;
                r[di][5] = hasR ? xr[4]  : 0.0f;
            } else {
#pragma unroll
                for (int t = 0; t < 6; t++) r[di][t] = 0.0f;
            }
        }

        float acc0 = 0.0f, acc1 = 0.0f, acc2 = 0.0f, acc3 = 0.0f;
#pragma unroll
        for (int di = 0; di < 3; di++) {
            float4 wl = wv[di * 3 + 0];   // weight for x[..][col-1]
            float4 wc = wv[di * 3 + 1];   // weight for x[..][col]
            float4 wr = wv[di * 3 + 2];   // weight for x[..][col+1]

            acc0 = fmaf(r[di][0], wl.x, acc0);
            acc0 = fmaf(r[di][1], wc.x, acc0);
            acc0 = fmaf(r[di][2], wr.x, acc0);

            acc1 = fmaf(r[di][1], wl.y, acc1);
            acc1 = fmaf(r[di][2], wc.y, acc1);
            acc1 = fmaf(r[di][3], wr.y, acc1);

            acc2 = fmaf(r[di][2], wl.z, acc2);
            acc2 = fmaf(r[di][3], wc.z, acc2);
            acc2 = fmaf(r[di][4], wr.z, acc2);

            acc3 = fmaf(r[di][3], wl.w, acc3);
            acc3 = fmaf(r[di][4], wc.w, acc3);
            acc3 = fmaf(r[di][5], wr.w, acc3);
        }

        float4 o;
        o.x = acc0; o.y = acc1; o.z = acc2; o.w = acc3;
        *reinterpret_cast<float4*>(ob + (size_t)c * HW_ + h * W_ + col0) = o;
    }
}

extern "C" void kernel_launch(void* const* d_in, const int* in_sizes, int n_in,
                              void* d_out, int out_size) {
    const float* x = (const float*)d_in[0];
    const float* w = (const float*)d_in[1];
    float* out = (float*)d_out;

    int total = B_ * CW_ * H_ * (W_ / 4);   // 262144
    int threads = 256;
    int blocks = total / threads;           // 1024
    ska_kernel<<<blocks, threads>>>(x, w, out);
}

// round 2
// speedup vs baseline: 1.1778x; 1.1778x over previous
#include <cuda_runtime.h>
#include <cuda_bf16.h>

// SKA: spatially-varying 3x3 grouped conv.
// x: (B=8, C=64, H=128, W=128) f32
// w: (B=8, C_w=8, 9, H, W) f32
// out[b, g*8+cw, h, col] = sum_{i,j} x_pad[b, g*8+cw, h+i-1, col+j-1] * w[b, cw, i*3+j, h, col]
//
// Warp = (b, cw, h); lane = 4-wide column chunk (32 lanes x 4 = W=128, full row).
// Horizontal halo exchanged via warp shuffle (lanes 0/31 are true image borders -> zero).
// 9 per-pixel weights (float4) loaded once and reused across all 8 groups.

#define B_   8
#define C_   64
#define H_   128
#define W_   128
#define CW_  8
#define G_   8
#define HW_  (H_ * W_)

__global__ void __launch_bounds__(256) ska_kernel(
    const float* __restrict__ x,
    const float* __restrict__ w,
    float* __restrict__ out)
{
    int gid  = blockIdx.x * blockDim.x + threadIdx.x;
    int lane = gid & 31;        // column chunk, == laneid
    int h    = (gid >> 5) & 127;
    int cw   = (gid >> 12) & 7;
    int b    = gid >> 15;
    int col0 = lane << 2;

    // ---- load the 9 per-pixel weights (float4 across 4 output columns) ----
    const float* wbase = w + ((size_t)(b * CW_ + cw) * 9) * HW_ + h * W_ + col0;
    float4 wv[9];
#pragma unroll
    for (int k = 0; k < 9; k++) {
        wv[k] = *reinterpret_cast<const float4*>(wbase + (size_t)k * HW_);
    }

    const float* xb = x + (size_t)b * C_ * HW_;
    float* ob = out + (size_t)b * C_ * HW_;

    // row validity is warp-uniform (h same across warp)
    const bool top = (h > 0);
    const bool bot = (h < H_ - 1);

#pragma unroll 2
    for (int g = 0; g < G_; g++) {
        int c = g * CW_ + cw;
        const float* xrow = xb + (size_t)c * HW_ + h * W_ + col0;

        float4 v[3];
        v[0] = top ? *reinterpret_cast<const float4*>(xrow - W_) : make_float4(0.f, 0.f, 0.f, 0.f);
        v[1] = *reinterpret_cast<const float4*>(xrow);
        v[2] = bot ? *reinterpret_cast<const float4*>(xrow + W_) : make_float4(0.f, 0.f, 0.f, 0.f);

        float acc0 = 0.f, acc1 = 0.f, acc2 = 0.f, acc3 = 0.f;
#pragma unroll
        for (int di = 0; di < 3; di++) {
            // horizontal halo via shuffle; lanes 0/31 are true image borders
            float L = __shfl_up_sync(0xffffffffu, v[di].w, 1);
            float R = __shfl_down_sync(0xffffffffu, v[di].x, 1);
            if (lane == 0)  L = 0.f;
            if (lane == 31) R = 0.f;

            float4 wl = wv[di * 3 + 0];
            float4 wc = wv[di * 3 + 1];
            float4 wr = wv[di * 3 + 2];

            acc0 = fmaf(L,       wl.x, acc0);
            acc0 = fmaf(v[di].x, wc.x, acc0);
            acc0 = fmaf(v[di].y, wr.x, acc0);

            acc1 = fmaf(v[di].x, wl.y, acc1);
            acc1 = fmaf(v[di].y, wc.y, acc1);
            acc1 = fmaf(v[di].z, wr.y, acc1);

            acc2 = fmaf(v[di].y, wl.z, acc2);
            acc2 = fmaf(v[di].z, wc.z, acc2);
            acc2 = fmaf(v[di].w, wr.z, acc2);

            acc3 = fmaf(v[di].z, wl.w, acc3);
            acc3 = fmaf(v[di].w, wc.w, acc3);
            acc3 = fmaf(R,       wr.w, acc3);
        }

        float4 o;
        o.x = acc0; o.y = acc1; o.z = acc2; o.w = acc3;
        *reinterpret_cast<float4*>(ob + (size_t)c * HW_ + h * W_ + col0) = o;
    }
}

extern "C" void kernel_launch(void* const* d_in, const int* in_sizes, int n_in,
                              void* d_out, int out_size) {
    const float* x = (const float*)d_in[0];
    const float* w = (const float*)d_in[1];
    float* out = (float*)d_out;

    int total = B_ * CW_ * H_ * (W_ / 4);   // 262144
    int threads = 256;
    int blocks = total / threads;           // 1024
    ska_kernel<<<blocks, threads>>>(x, w, out);
}

// round 3
// speedup vs baseline: 1.1794x; 1.0014x over previous
#include <cuda_runtime.h>
#include <cuda_bf16.h>

// SKA: spatially-varying 3x3 grouped conv.
// x: (B=8, C=64, H=128, W=128) f32
// w: (B=8, C_w=8, 9, H, W) f32
// out[b, g*8+cw, h, col] = sum_{i,j} x_pad[b, g*8+cw, h+i-1, col+j-1] * w[b, cw, i*3+j, h, col]
//
// Warp = (b, cw, h); lane = 4-wide column chunk (32 lanes x 4 = W=128, full row).
// Horizontal halo exchanged via warp shuffle (lanes 0/31 are true image borders -> zero).
// 9 per-pixel weights (float4) loaded once and reused across all 8 groups.

#define B_   8
#define C_   64
#define H_   128
#define W_   128
#define CW_  8
#define G_   8
#define HW_  (H_ * W_)

__global__ void __launch_bounds__(256) ska_kernel(
    const float* __restrict__ x,
    const float* __restrict__ w,
    float* __restrict__ out)
{
    int gid  = blockIdx.x * blockDim.x + threadIdx.x;
    int lane = gid & 31;        // column chunk, == laneid
    int h    = (gid >> 5) & 127;
    int cw   = (gid >> 12) & 7;
    int b    = gid >> 15;
    int col0 = lane << 2;

    // ---- load the 9 per-pixel weights (float4 across 4 output columns) ----
    const float* wbase = w + ((size_t)(b * CW_ + cw) * 9) * HW_ + h * W_ + col0;
    float4 wv[9];
#pragma unroll
    for (int k = 0; k < 9; k++) {
        wv[k] = *reinterpret_cast<const float4*>(wbase + (size_t)k * HW_);
    }

    const float* xb = x + (size_t)b * C_ * HW_;
    float* ob = out + (size_t)b * C_ * HW_;

    // row validity is warp-uniform (h same across warp)
    const bool top = (h > 0);
    const bool bot = (h < H_ - 1);

#pragma unroll 2
    for (int g = 0; g < G_; g++) {
        int c = g * CW_ + cw;
        const float* xrow = xb + (size_t)c * HW_ + h * W_ + col0;

        float4 v[3];
        v[0] = top ? *reinterpret_cast<const float4*>(xrow - W_) : make_float4(0.f, 0.f, 0.f, 0.f);
        v[1] = *reinterpret_cast<const float4*>(xrow);
        v[2] = bot ? *reinterpret_cast<const float4*>(xrow + W_) : make_float4(0.f, 0.f, 0.f, 0.f);

        float acc0 = 0.f, acc1 = 0.f, acc2 = 0.f, acc3 = 0.f;
#pragma unroll
        for (int di = 0; di < 3; di++) {
            // horizontal halo via shuffle; lanes 0/31 are true image borders
            float L = __shfl_up_sync(0xffffffffu, v[di].w, 1);
            float R = __shfl_down_sync(0xffffffffu, v[di].x, 1);
            if (lane == 0)  L = 0.f;
            if (lane == 31) R = 0.f;

            float4 wl = wv[di * 3 + 0];
            float4 wc = wv[di * 3 + 1];
            float4 wr = wv[di * 3 + 2];

            acc0 = fmaf(L,       wl.x, acc0);
            acc0 = fmaf(v[di].x, wc.x, acc0);
            acc0 = fmaf(v[di].y, wr.x, acc0);

            acc1 = fmaf(v[di].x, wl.y, acc1);
            acc1 = fmaf(v[di].y, wc.y, acc1);
            acc1 = fmaf(v[di].z, wr.y, acc1);

            acc2 = fmaf(v[di].y, wl.z, acc2);
            acc2 = fmaf(v[di].z, wc.z, acc2);
            acc2 = fmaf(v[di].w, wr.z, acc2);

            acc3 = fmaf(v[di].z, wl.w, acc3);
            acc3 = fmaf(v[di].w, wc.w, acc3);
            acc3 = fmaf(R,       wr.w, acc3);
        }

        float4 o;
        o.x = acc0; o.y = acc1; o.z = acc2; o.w = acc3;
        *reinterpret_cast<float4*>(ob + (size_t)c * HW_ + h * W_ + col0) = o;
    }
}

extern "C" void kernel_launch(void* const* d_in, const int* in_sizes, int n_in,
                              void* d_out, int out_size) {
    const float* x = (const float*)d_in[0];
    const float* w = (const float*)d_in[1];
    float* out = (float*)d_out;

    int total = B_ * CW_ * H_ * (W_ / 4);   // 262144
    int threads = 256;
    int blocks = total / threads;           // 1024
    ska_kernel<<<blocks, threads>>>(x, w, out);
}

// round 4
// speedup vs baseline: 1.1961x; 1.0141x over previous
#include <cuda_runtime.h>
#include <cuda_bf16.h>

// SKA: spatially-varying 3x3 grouped conv.
// x: (B=8, C=64, H=128, W=128) f32
// w: (B=8, C_w=8, 9, H, W) f32
// out[b, g*8+cw, h, col] = sum_{i,j} x_pad[b, g*8+cw, h+i-1, col+j-1] * w[b, cw, i*3+j, h, col]
//
// Warp = (b, cw, h); lane = 4-wide column chunk (32 lanes x 4 = W=128 full row).
// Horizontal halo via warp shuffle. 9 per-pixel weights loaded once, reused
// across all 8 groups. Groups processed in batches of 4: 12 independent x-row
// loads issued up front per batch to maximize MLP (latency-bound kernel).

#define B_   8
#define C_   64
#define H_   128
#define W_   128
#define CW_  8
#define G_   8
#define HW_  (H_ * W_)

__global__ void __launch_bounds__(256) ska_kernel(
    const float* __restrict__ x,
    const float* __restrict__ w,
    float* __restrict__ out)
{
    int gid  = blockIdx.x * blockDim.x + threadIdx.x;
    int lane = gid & 31;        // column chunk, == laneid
    int h    = (gid >> 5) & 127;
    int cw   = (gid >> 12) & 7;
    int b    = gid >> 15;
    int col0 = lane << 2;

    // ---- load the 9 per-pixel weights (float4 across 4 output columns) ----
    const float* wbase = w + ((size_t)(b * CW_ + cw) * 9) * HW_ + h * W_ + col0;
    float4 wv[9];
#pragma unroll
    for (int k = 0; k < 9; k++) {
        wv[k] = *reinterpret_cast<const float4*>(wbase + (size_t)k * HW_);
    }

    const float* xb = x + (size_t)b * C_ * HW_;
    float* ob = out + (size_t)b * C_ * HW_;

    // row validity is warp-uniform (h same across warp)
    const bool top = (h > 0);
    const bool bot = (h < H_ - 1);
    const float4 z4 = make_float4(0.f, 0.f, 0.f, 0.f);

#pragma unroll
    for (int gg = 0; gg < G_; gg += 4) {
        // ---- batch-load 4 groups x 3 rows = 12 independent LDG.128 ----
        float4 v[4][3];
#pragma unroll
        for (int q = 0; q < 4; q++) {
            int c = (gg + q) * CW_ + cw;
            const float* xrow = xb + (size_t)c * HW_ + h * W_ + col0;
            v[q][0] = top ? *reinterpret_cast<const float4*>(xrow - W_) : z4;
            v[q][1] = *reinterpret_cast<const float4*>(xrow);
            v[q][2] = bot ? *reinterpret_cast<const float4*>(xrow + W_) : z4;
        }

        // ---- compute + store the 4 groups ----
#pragma unroll
        for (int q = 0; q < 4; q++) {
            int c = (gg + q) * CW_ + cw;
            float acc0 = 0.f, acc1 = 0.f, acc2 = 0.f, acc3 = 0.f;
#pragma unroll
            for (int di = 0; di < 3; di++) {
                float L = __shfl_up_sync(0xffffffffu, v[q][di].w, 1);
                float R = __shfl_down_sync(0xffffffffu, v[q][di].x, 1);
                if (lane == 0)  L = 0.f;
                if (lane == 31) R = 0.f;

                float4 wl = wv[di * 3 + 0];
                float4 wc = wv[di * 3 + 1];
                float4 wr = wv[di * 3 + 2];

                acc0 = fmaf(L,          wl.x, acc0);
                acc0 = fmaf(v[q][di].x, wc.x, acc0);
                acc0 = fmaf(v[q][di].y, wr.x, acc0);

                acc1 = fmaf(v[q][di].x, wl.y, acc1);
                acc1 = fmaf(v[q][di].y, wc.y, acc1);
                acc1 = fmaf(v[q][di].z, wr.y, acc1);

                acc2 = fmaf(v[q][di].y, wl.z, acc2);
                acc2 = fmaf(v[q][di].z, wc.z, acc2);
                acc2 = fmaf(v[q][di].w, wr.z, acc2);

                acc3 = fmaf(v[q][di].z, wl.w, acc3);
                acc3 = fmaf(v[q][di].w, wc.w, acc3);
                acc3 = fmaf(R,          wr.w, acc3);
            }

            float4 o;
            o.x = acc0; o.y = acc1; o.z = acc2; o.w = acc3;
            *reinterpret_cast<float4*>(ob + (size_t)c * HW_ + h * W_ + col0) = o;
        }
    }
}

extern "C" void kernel_launch(void* const* d_in, const int* in_sizes, int n_in,
                              void* d_out, int out_size) {
    const float* x = (const float*)d_in[0];
    const float* w = (const float*)d_in[1];
    float* out = (float*)d_out;

    int total = B_ * CW_ * H_ * (W_ / 4);   // 262144
    int threads = 256;
    int blocks = total / threads;           // 1024
    ska_kernel<<<blocks, threads>>>(x, w, out);
}